// round 15
// baseline (speedup 1.0000x reference)
#include <cuda_runtime.h>
#include <cuda_fp16.h>
#include <math.h>
#include <stdint.h>

// Problem dims (fixed by the dataset)
#define B_ 64
#define S_ 1024
#define D_ 512
#define F_ 256
#define H_ 512

// ---------------------------------------------------------------------------
// Scratch (__device__ globals; no allocations allowed)
// ---------------------------------------------------------------------------
__device__ float g_stf[B_ * H_];
__device__ float g_stx[B_ * H_];
__device__ float g_se4[4 * S_ * B_];   // partial scores, one slab per N-block
__device__ float g_sf4[4 * S_ * B_];
__device__ float g_ctx4[4][B_ * D_];   // partial contexts, one slab per S-quarter
// fp16 transposed weights, exact split: W = Wh + Wl  ([H][K] each)
__device__ __half g_Weh[H_ * D_];
__device__ __half g_Wel[H_ * D_];
__device__ __half g_Wfh[H_ * F_];
__device__ __half g_Wfl[H_ * F_];
// fp16 activations: [B,S,K]
__device__ __half g_Aeh[B_ * S_ * D_];
__device__ __half g_Afh[B_ * S_ * F_];

// ---------------------------------------------------------------------------
// PTX helpers (sm_80-baseline; legal on plain sm_103 target)
// ---------------------------------------------------------------------------
__device__ __forceinline__ uint32_t smem_u32(const void* p) {
    uint32_t a;
    asm("{ .reg .u64 t; cvta.to.shared.u64 t, %1; cvt.u32.u64 %0, t; }" : "=r"(a) : "l"(p));
    return a;
}

// NOTE: intentionally NOT volatile — pure register op; lets ptxas schedule.
__device__ __forceinline__ void mma_f16(float* c, const uint32_t* a,
                                        uint32_t b0, uint32_t b1) {
    asm("mma.sync.aligned.m16n8k16.row.col.f32.f16.f16.f32 "
        "{%0,%1,%2,%3}, {%4,%5,%6,%7}, {%8,%9}, {%0,%1,%2,%3};\n"
        : "+f"(c[0]), "+f"(c[1]), "+f"(c[2]), "+f"(c[3])
        : "r"(a[0]), "r"(a[1]), "r"(a[2]), "r"(a[3]), "r"(b0), "r"(b1));
}

__device__ __forceinline__ void ldsm_x4(uint32_t* r, uint32_t addr) {
    asm volatile("ldmatrix.sync.aligned.m8n8.x4.shared.b16 {%0,%1,%2,%3}, [%4];"
                 : "=r"(r[0]), "=r"(r[1]), "=r"(r[2]), "=r"(r[3]) : "r"(addr));
}

#define CP16(dst, src) \
    asm volatile("cp.async.cg.shared.global [%0], [%1], 16;" :: "r"(dst), "l"(src))
#define CP_COMMIT() asm volatile("cp.async.commit_group;" ::: "memory")
#define CP_WAIT1()  asm volatile("cp.async.wait_group 1;" ::: "memory")
#define CP_WAIT0()  asm volatile("cp.async.wait_group 0;" ::: "memory")

// ---------------------------------------------------------------------------
// W convert+transpose, exact fp16 split: W[K][H] fp32 -> Wh,Wl [H][K] fp16
// ---------------------------------------------------------------------------
__global__ void wconv_kernel(const float* __restrict__ W,
                             __half* __restrict__ Wh,
                             __half* __restrict__ Wl, int K)
{
    int h = blockIdx.x;
    for (int k = threadIdx.x; k < K; k += blockDim.x) {
        float v = W[(size_t)k * H_ + h];
        __half hi = __float2half_rn(v);
        float lo = v - __half2float(hi);
        Wh[(size_t)h * K + k] = hi;
        Wl[(size_t)h * K + k] = __float2half_rn(lo);
    }
}

// ---------------------------------------------------------------------------
// A convert (coalesced, memory-bound): A fp32 -> Ah fp16, same layout
// ---------------------------------------------------------------------------
__global__ void aconv_kernel(const float* __restrict__ A,
                             __half* __restrict__ Ah)
{
    size_t i = (size_t)blockIdx.x * blockDim.x + threadIdx.x;   // float4 index
    float4 v = ((const float4*)A)[i];
    uint2 hv;
    __half2 t01, t23;
    t01.x = __float2half_rn(v.x); t01.y = __float2half_rn(v.y);
    t23.x = __float2half_rn(v.z); t23.y = __float2half_rn(v.w);
    hv.x = *reinterpret_cast<uint32_t*>(&t01);
    hv.y = *reinterpret_cast<uint32_t*>(&t23);
    ((uint2*)Ah)[i] = hv;
}

// ---------------------------------------------------------------------------
// K1: state vectors
// ---------------------------------------------------------------------------
__global__ void state_kernel(const float* __restrict__ x,
                             const float* __restrict__ Wsf, const float* __restrict__ bsf,
                             const float* __restrict__ Wse, const float* __restrict__ bse)
{
    __shared__ float xs[D_];
    int b = blockIdx.x, h = threadIdx.x;
    xs[h] = x[b * D_ + h];
    __syncthreads();
    float a0 = bsf[h], a1 = bse[h];
#pragma unroll 8
    for (int k = 0; k < D_; k++) {
        float xv = xs[k];
        a0 += xv * Wsf[k * H_ + h];
        a1 += xv * Wse[k * H_ + h];
    }
    g_stf[b * H_ + h] = tanhf(a0);
    g_stx[b * H_ + h] = tanhf(a1);
}

// ---------------------------------------------------------------------------
// K2: fused score GEMM, 2-MMA exact-W scheme, BK=64.
//   partial[z][s,b] = sum_{h in z-block} tanh(A[b,s,:]@W[:,h]+bias[h])*state[b,h]
// 256 thr (4(M) x 2(N) warps), M=128, N-block=128 (blockIdx.z), BK=64.
// SMEM: bias 512B | st 512B | partial 512B | pad | 2 stages x 55296
//   stage: A +0, Wh +18432, Wl +36864 (rows 128B data padded to 144B)
// Inner loop: hi-pass over 8 accumulators then lo-pass (RAW distance 8;
// per-accumulator FLOP order unchanged -> bit-exact vs R14).
// ---------------------------------------------------------------------------
static constexpr uint32_t STG_STRIDE = 55296;
static constexpr uint32_t TILES_OFF  = 2048;
static constexpr uint32_t SMEM_DYN   = TILES_OFF + 2 * STG_STRIDE;  // 112640

template<int K, int PHASE>
__global__ __launch_bounds__(256, 2) void score_mma(
    const __half* __restrict__ Ah_g,     // [B_,S_,K]
    const __half* __restrict__ Wh,       // [H_,K]
    const __half* __restrict__ Wl,       // [H_,K]
    const float* __restrict__ bias)
{
    extern __shared__ char smem[];
    float* bias_sh    = (float*)smem;            // 128 floats (this N-block)
    float* st_sh      = (float*)(smem + 512);    // 128 floats
    float* partial_sh = (float*)(smem + 1024);   // 128 floats

    const int tid  = threadIdx.x;
    const int lane = tid & 31;
    const int wid  = tid >> 5;
    const int warpM = wid & 3;
    const int warpN = wid >> 2;
    const int g = lane >> 2;
    const int t = lane & 3;

    const int b  = blockIdx.y;
    const int s0 = blockIdx.x * 128;
    const int h0 = blockIdx.z * 128;

    const uint32_t tbase = smem_u32(smem) + TILES_OFF;

    const float* __restrict__ st = (PHASE == 0 ? g_stx : g_stf) + b * H_;
    if (tid < 128) { bias_sh[tid] = bias[h0 + tid]; st_sh[tid] = st[h0 + tid]; }

    const __half* __restrict__ Abh = Ah_g + ((size_t)b * S_ + s0) * K;

    float acc[2][8][4];
#pragma unroll
    for (int mt = 0; mt < 2; mt++)
#pragma unroll
        for (int nt = 0; nt < 8; nt++)
#pragma unroll
            for (int j = 0; j < 4; j++) acc[mt][nt][j] = 0.f;

    // Each 128x64 fp16 buffer = 1024 16B-chunks; 4 per thread per buffer.
    auto issue = [&](int ki, int buf) {
        const uint32_t base = tbase + (uint32_t)buf * STG_STRIDE;
        const int k0 = ki * 64;
#pragma unroll
        for (int p = 0; p < 4; p++) {
            int idx = p * 256 + tid;
            int r = idx >> 3, c = idx & 7;
            uint32_t doff = (uint32_t)r * 144 + c * 16;
            CP16(base +         doff, Abh + (size_t)r * K + k0 + c * 8);
            CP16(base + 18432 + doff, Wh + (size_t)(h0 + r) * K + k0 + c * 8);
            CP16(base + 36864 + doff, Wl + (size_t)(h0 + r) * K + k0 + c * 8);
        }
    };

    constexpr int NK = K / 64;

    issue(0, 0);
    CP_COMMIT();

    for (int ki = 0; ki < NK; ki++) {
        if (ki > 0) __syncthreads();   // all warps done with stage ki-1 before buf reuse
        if (ki + 1 < NK) {
            issue(ki + 1, (ki + 1) & 1);
            CP_COMMIT();
            CP_WAIT1();    // stage ki landed; ki+1 in flight
        } else {
            CP_WAIT0();
        }
        __syncthreads();   // tile visible to all warps

        const uint32_t sb = tbase + (uint32_t)(ki & 1) * STG_STRIDE;
#pragma unroll
        for (int kk = 0; kk < 4; kk++) {
            const int kb = kk * 16;     // fp16 elems within the 64-wide tile
            uint32_t ah[2][4];
#pragma unroll
            for (int mt = 0; mt < 2; mt++) {
                int row = warpM * 32 + mt * 16 + (lane & 15);
                uint32_t a_addr = sb + (uint32_t)row * 144
                                + ((uint32_t)kb + ((lane >> 4) << 3)) * 2;
                ldsm_x4(ah[mt], a_addr);
            }
#pragma unroll
            for (int ntg = 0; ntg < 2; ntg++) {
                int nrow = warpN * 64 + ntg * 32 + lane;
                uint32_t b_addr = sb + 18432 + (uint32_t)nrow * 144 + kb * 2;
                uint32_t bh0[4], bh1[4], bl0[4], bl1[4];
                ldsm_x4(bh0, b_addr);
                ldsm_x4(bh1, b_addr + 16);
                ldsm_x4(bl0, b_addr + 18432);
                ldsm_x4(bl1, b_addr + 18432 + 16);
                // hi pass: 8 independent accumulators (RAW distance = 8)
#pragma unroll
                for (int i = 0; i < 4; i++)
#pragma unroll
                    for (int mt = 0; mt < 2; mt++)
                        mma_f16(acc[mt][ntg * 4 + i], ah[mt], bh0[i], bh1[i]);
                // lo pass: same accumulators, same per-acc order (hi then lo)
#pragma unroll
                for (int i = 0; i < 4; i++)
#pragma unroll
                    for (int mt = 0; mt < 2; mt++)
                        mma_f16(acc[mt][ntg * 4 + i], ah[mt], bl0[i], bl1[i]);
            }
        }
    }

    // ---- epilogue: tanh(+bias) . state over this CTA's 128 h ----
    float scoreRow[4] = {0.f, 0.f, 0.f, 0.f};
#pragma unroll
    for (int mt = 0; mt < 2; mt++)
#pragma unroll
        for (int nt = 0; nt < 8; nt++)
#pragma unroll
            for (int j = 0; j < 4; j++) {
                int hh = warpN * 64 + nt * 8 + 2 * t + (j & 1);
                float v = tanhf(acc[mt][nt][j] + bias_sh[hh]) * st_sh[hh];
                scoreRow[mt * 2 + (j >> 1)] += v;
            }

    // Reduce across the 4 t-lanes of each quad (same row g)
#pragma unroll
    for (int off = 1; off < 4; off <<= 1)
#pragma unroll
        for (int i = 0; i < 4; i++)
            scoreRow[i] += __shfl_xor_sync(0xffffffffu, scoreRow[i], off);

    // Combine warpN halves via smem, write this z-slab's partial scores
    __syncthreads();
    if (t == 0 && warpN == 1) {
#pragma unroll
        for (int mt = 0; mt < 2; mt++)
#pragma unroll
            for (int rh = 0; rh < 2; rh++) {
                int r = warpM * 32 + mt * 16 + rh * 8 + g;
                partial_sh[r] = scoreRow[mt * 2 + rh];
            }
    }
    __syncthreads();
    if (t == 0 && warpN == 0) {
        float* scoreOut = (PHASE == 0 ? g_se4 : g_sf4) + (size_t)blockIdx.z * (S_ * B_);
#pragma unroll
        for (int mt = 0; mt < 2; mt++)
#pragma unroll
            for (int rh = 0; rh < 2; rh++) {
                int r = warpM * 32 + mt * 16 + rh * 8 + g;
                scoreOut[(size_t)(s0 + r) * B_ + b] =
                    scoreRow[mt * 2 + rh] + partial_sh[r];
            }
    }
}

// ---------------------------------------------------------------------------
// K3: dual softmax + gamma (sums the 4 partial-score slabs, fixed order)
// ---------------------------------------------------------------------------
__global__ void gamma_kernel(float* __restrict__ gamma_out)
{
    __shared__ float red[256];
    __shared__ float tbuf[S_];
    const int b = blockIdx.x, tid = threadIdx.x;
    constexpr int SB = S_ * B_;

    float se[4], sf[4];
    float mE = -1e30f, mF = -1e30f;
#pragma unroll
    for (int i = 0; i < 4; i++) {
        int s = tid + i * 256;
        int idx = s * B_ + b;
        se[i] = ((g_se4[idx] + g_se4[SB + idx]) + (g_se4[2 * SB + idx] + g_se4[3 * SB + idx]));
        sf[i] = ((g_sf4[idx] + g_sf4[SB + idx]) + (g_sf4[2 * SB + idx] + g_sf4[3 * SB + idx]));
        mE = fmaxf(mE, se[i]);
        mF = fmaxf(mF, sf[i]);
    }
    auto blockMax = [&](float v) -> float {
        red[tid] = v; __syncthreads();
        for (int st = 128; st > 0; st >>= 1) {
            if (tid < st) red[tid] = fmaxf(red[tid], red[tid + st]);
            __syncthreads();
        }
        float r = red[0]; __syncthreads(); return r;
    };
    auto blockSum = [&](float v) -> float {
        red[tid] = v; __syncthreads();
        for (int st = 128; st > 0; st >>= 1) {
            if (tid < st) red[tid] += red[tid + st];
            __syncthreads();
        }
        float r = red[0]; __syncthreads(); return r;
    };
    mE = blockMax(mE);
    mF = blockMax(mF);

    float ze = 0.f, zf = 0.f, p = 0.f;
#pragma unroll
    for (int i = 0; i < 4; i++) {
        float ee = expf(se[i] - mE);
        float ef = expf(sf[i] - mF);
        ze += ee; zf += ef;
        float t = ee * ef;
        p += t;
        tbuf[tid + i * 256] = t;
    }
    ze = blockSum(ze);
    zf = blockSum(zf);
    p  = blockSum(p);

    float inv = 1.0f / (p + 1e-6f * ze * zf);
#pragma unroll
    for (int i = 0; i < 4; i++) {
        int s = tid + i * 256;
        gamma_out[s * B_ + b] = tbuf[s] * inv;
    }
}

// ---------------------------------------------------------------------------
// K4: context, S split 4 ways across blockIdx.y (partial slabs)
// ---------------------------------------------------------------------------
__global__ void context_kernel(const float* __restrict__ enc,
                               const float* __restrict__ gamma)
{
    __shared__ float gs[256];
    const int b = blockIdx.x, q = blockIdx.y, d = threadIdx.x;
    if (d < 256) gs[d] = gamma[(q * 256 + d) * B_ + b];
    __syncthreads();
    const float* __restrict__ e = enc + ((size_t)b * S_ + q * 256) * D_;
    float acc = 0.f;
#pragma unroll 4
    for (int s = 0; s < 256; s++)
        acc += gs[s] * e[(size_t)s * D_ + d];
    g_ctx4[q][b * D_ + d] = acc;
}

// ---------------------------------------------------------------------------
// K5: output GEMM + tanh (sums the 4 context slabs, fixed order)
// ---------------------------------------------------------------------------
__global__ void out_kernel(const float* __restrict__ x,
                           const float* __restrict__ Wg, const float* __restrict__ bg,
                           float* __restrict__ out)
{
    __shared__ float cx[2 * D_];
    const int b = blockIdx.x, h = threadIdx.x;
    cx[h] = (g_ctx4[0][b * D_ + h] + g_ctx4[1][b * D_ + h])
          + (g_ctx4[2][b * D_ + h] + g_ctx4[3][b * D_ + h]);
    cx[D_ + h] = x[b * D_ + h];
    __syncthreads();
    float acc = bg[h];
#pragma unroll 8
    for (int k = 0; k < 2 * D_; k++)
        acc += cx[k] * Wg[(size_t)k * H_ + h];
    out[b * H_ + h] = tanhf(acc);
}

// ---------------------------------------------------------------------------
extern "C" void kernel_launch(void* const* d_in, const int* in_sizes, int n_in,
                              void* d_out, int out_size)
{
    const float* x    = (const float*)d_in[0];
    const float* enc  = (const float*)d_in[1];
    const float* fld  = (const float*)d_in[2];
    const float* Wf   = (const float*)d_in[3];
    const float* bf   = (const float*)d_in[4];
    const float* We   = (const float*)d_in[5];
    const float* be   = (const float*)d_in[6];
    const float* Wsf  = (const float*)d_in[7];
    const float* bsf  = (const float*)d_in[8];
    const float* Wse  = (const float*)d_in[9];
    const float* bse  = (const float*)d_in[10];
    const float* Wg   = (const float*)d_in[11];
    const float* bg   = (const float*)d_in[12];

    float* out    = (float*)d_out;
    float* gammas = out + B_ * H_;

    static cudaStream_t s1 = nullptr, s2 = nullptr;
    static cudaEvent_t evFork = nullptr, evState = nullptr, evF = nullptr;
    static int init_done = 0;
    if (!init_done) {
        cudaFuncSetAttribute(score_mma<D_, 0>,
                             cudaFuncAttributeMaxDynamicSharedMemorySize, SMEM_DYN);
        cudaFuncSetAttribute(score_mma<F_, 1>,
                             cudaFuncAttributeMaxDynamicSharedMemorySize, SMEM_DYN);
        cudaStreamCreateWithFlags(&s1, cudaStreamNonBlocking);
        cudaStreamCreateWithFlags(&s2, cudaStreamNonBlocking);
        cudaEventCreateWithFlags(&evFork,  cudaEventDisableTiming);
        cudaEventCreateWithFlags(&evState, cudaEventDisableTiming);
        cudaEventCreateWithFlags(&evF,     cudaEventDisableTiming);
        init_done = 1;
    }

    // Resolve device-global addresses (host-side, no allocation)
    __half *pWeh, *pWel, *pWfh, *pWfl, *pAeh, *pAfh;
    cudaGetSymbolAddress((void**)&pWeh, g_Weh);
    cudaGetSymbolAddress((void**)&pWel, g_Wel);
    cudaGetSymbolAddress((void**)&pWfh, g_Wfh);
    cudaGetSymbolAddress((void**)&pWfl, g_Wfl);
    cudaGetSymbolAddress((void**)&pAeh, g_Aeh);
    cudaGetSymbolAddress((void**)&pAfh, g_Afh);

    // Fork s1 (fields branch) and s2 (state) off the default stream.
    cudaEventRecord(evFork, 0);
    cudaStreamWaitEvent(s1, evFork, 0);
    cudaStreamWaitEvent(s2, evFork, 0);

    // default stream: enc branch
    wconv_kernel<<<H_, 256>>>(We, pWeh, pWel, D_);
    aconv_kernel<<<(B_ * S_ * D_) / 1024, 256>>>(enc, pAeh);

    // s1: fields branch
    wconv_kernel<<<H_, 256, 0, s1>>>(Wf, pWfh, pWfl, F_);
    aconv_kernel<<<(B_ * S_ * F_) / 1024, 256, 0, s1>>>(fld, pAfh);

    // s2: state vectors (needed by both score kernels)
    state_kernel<<<B_, 512, 0, s2>>>(x, Wsf, bsf, Wse, bse);
    cudaEventRecord(evState, s2);
    cudaStreamWaitEvent(0, evState, 0);
    cudaStreamWaitEvent(s1, evState, 0);

    // Score GEMMs run concurrently on the two streams
    dim3 sgrid(S_ / 128, B_, 4);
    score_mma<D_, 0><<<sgrid, 256, SMEM_DYN>>>(pAeh, pWeh, pWel, be);
    score_mma<F_, 1><<<sgrid, 256, SMEM_DYN, s1>>>(pAfh, pWfh, pWfl, bf);
    cudaEventRecord(evF, s1);
    cudaStreamWaitEvent(0, evF, 0);

    // Join: softmax/gamma -> context -> output (default stream)
    gamma_kernel<<<B_, 256>>>(gammas);
    dim3 cgrid(B_, 4);
    context_kernel<<<cgrid, 512>>>(enc, gammas);
    out_kernel<<<B_, 512>>>(x, Wg, bg, out);
}

// round 16
// speedup vs baseline: 1.0172x; 1.0172x over previous
#include <cuda_runtime.h>
#include <cuda_fp16.h>
#include <math.h>
#include <stdint.h>

// Problem dims (fixed by the dataset)
#define B_ 64
#define S_ 1024
#define D_ 512
#define F_ 256
#define H_ 512

// ---------------------------------------------------------------------------
// Scratch (__device__ globals; no allocations allowed)
// ---------------------------------------------------------------------------
__device__ float g_stf[B_ * H_];
__device__ float g_stx[B_ * H_];
__device__ float g_se4[4 * S_ * B_];   // partial scores, one slab per N-block
__device__ float g_sf4[4 * S_ * B_];
__device__ float g_ctx4[4][B_ * D_];   // partial contexts, one slab per S-quarter
// fp16 transposed weights, exact split: W = Wh + Wl  ([H][K] each)
__device__ __half g_Weh[H_ * D_];
__device__ __half g_Wel[H_ * D_];
__device__ __half g_Wfh[H_ * F_];
__device__ __half g_Wfl[H_ * F_];
// fp16 activations: [B,S,K]
__device__ __half g_Aeh[B_ * S_ * D_];
__device__ __half g_Afh[B_ * S_ * F_];

// ---------------------------------------------------------------------------
// PTX helpers (sm_80-baseline; legal on plain sm_103 target)
// ---------------------------------------------------------------------------
__device__ __forceinline__ uint32_t smem_u32(const void* p) {
    uint32_t a;
    asm("{ .reg .u64 t; cvta.to.shared.u64 t, %1; cvt.u32.u64 %0, t; }" : "=r"(a) : "l"(p));
    return a;
}

__device__ __forceinline__ void mma_f16(float* c, const uint32_t* a,
                                        uint32_t b0, uint32_t b1) {
    asm("mma.sync.aligned.m16n8k16.row.col.f32.f16.f16.f32 "
        "{%0,%1,%2,%3}, {%4,%5,%6,%7}, {%8,%9}, {%0,%1,%2,%3};\n"
        : "+f"(c[0]), "+f"(c[1]), "+f"(c[2]), "+f"(c[3])
        : "r"(a[0]), "r"(a[1]), "r"(a[2]), "r"(a[3]), "r"(b0), "r"(b1));
}

__device__ __forceinline__ void ldsm_x4(uint32_t* r, uint32_t addr) {
    asm volatile("ldmatrix.sync.aligned.m8n8.x4.shared.b16 {%0,%1,%2,%3}, [%4];"
                 : "=r"(r[0]), "=r"(r[1]), "=r"(r[2]), "=r"(r[3]) : "r"(addr));
}

#define CP16(dst, src) \
    asm volatile("cp.async.cg.shared.global [%0], [%1], 16;" :: "r"(dst), "l"(src))
#define CP_COMMIT() asm volatile("cp.async.commit_group;" ::: "memory")
#define CP_WAIT1()  asm volatile("cp.async.wait_group 1;" ::: "memory")
#define CP_WAIT0()  asm volatile("cp.async.wait_group 0;" ::: "memory")

// ---------------------------------------------------------------------------
// W convert+transpose, exact fp16 split: W[K][H] fp32 -> Wh,Wl [H][K] fp16
// ---------------------------------------------------------------------------
__global__ void wconv_kernel(const float* __restrict__ W,
                             __half* __restrict__ Wh,
                             __half* __restrict__ Wl, int K)
{
    int h = blockIdx.x;
    for (int k = threadIdx.x; k < K; k += blockDim.x) {
        float v = W[(size_t)k * H_ + h];
        __half hi = __float2half_rn(v);
        float lo = v - __half2float(hi);
        Wh[(size_t)h * K + k] = hi;
        Wl[(size_t)h * K + k] = __float2half_rn(lo);
    }
}

// ---------------------------------------------------------------------------
// A convert (coalesced, memory-bound): A fp32 -> Ah fp16, same layout
// ---------------------------------------------------------------------------
__global__ void aconv_kernel(const float* __restrict__ A,
                             __half* __restrict__ Ah)
{
    size_t i = (size_t)blockIdx.x * blockDim.x + threadIdx.x;   // float4 index
    float4 v = ((const float4*)A)[i];
    uint2 hv;
    __half2 t01, t23;
    t01.x = __float2half_rn(v.x); t01.y = __float2half_rn(v.y);
    t23.x = __float2half_rn(v.z); t23.y = __float2half_rn(v.w);
    hv.x = *reinterpret_cast<uint32_t*>(&t01);
    hv.y = *reinterpret_cast<uint32_t*>(&t23);
    ((uint2*)Ah)[i] = hv;
}

// ---------------------------------------------------------------------------
// K1: state vectors
// ---------------------------------------------------------------------------
__global__ void state_kernel(const float* __restrict__ x,
                             const float* __restrict__ Wsf, const float* __restrict__ bsf,
                             const float* __restrict__ Wse, const float* __restrict__ bse)
{
    __shared__ float xs[D_];
    int b = blockIdx.x, h = threadIdx.x;
    xs[h] = x[b * D_ + h];
    __syncthreads();
    float a0 = bsf[h], a1 = bse[h];
#pragma unroll 8
    for (int k = 0; k < D_; k++) {
        float xv = xs[k];
        a0 += xv * Wsf[k * H_ + h];
        a1 += xv * Wse[k * H_ + h];
    }
    g_stf[b * H_ + h] = tanhf(a0);
    g_stx[b * H_ + h] = tanhf(a1);
}

// ---------------------------------------------------------------------------
// K2: MERGED fused score GEMM (both phases in one launch).
//   blockIdx.z 0..3  -> enc path   (K=512, A=g_Aeh, W=Weh/Wel, st=g_stx -> g_se4)
//   blockIdx.z 4..7  -> fields path(K=256, A=g_Afh, W=Wfh/Wfl, st=g_stf -> g_sf4)
// 2-MMA exact-W scheme, BK=64, 256 thr (4(M) x 2(N) warps), M=128, N-block=128.
// SMEM: bias 512B | st 512B | partial 512B | pad | 2 stages x 55296
//   stage: A +0, Wh +18432, Wl +36864 (rows 128B data padded to 144B)
// Per-accumulator FLOP order identical to R13/R14 -> gammas bit-exact.
// ---------------------------------------------------------------------------
static constexpr uint32_t STG_STRIDE = 55296;
static constexpr uint32_t TILES_OFF  = 2048;
static constexpr uint32_t SMEM_DYN   = TILES_OFF + 2 * STG_STRIDE;  // 112640

__global__ __launch_bounds__(256, 2) void score_mma(
    const __half* __restrict__ Ae,      // [B_,S_,D_]
    const __half* __restrict__ Weh_,    // [H_,D_]
    const __half* __restrict__ Wel_,
    const float* __restrict__ be,
    const __half* __restrict__ Af,      // [B_,S_,F_]
    const __half* __restrict__ Wfh_,    // [H_,F_]
    const __half* __restrict__ Wfl_,
    const float* __restrict__ bf)
{
    extern __shared__ char smem[];
    float* bias_sh    = (float*)smem;            // 128 floats (this N-block)
    float* st_sh      = (float*)(smem + 512);    // 128 floats
    float* partial_sh = (float*)(smem + 1024);   // 128 floats

    const int tid  = threadIdx.x;
    const int lane = tid & 31;
    const int wid  = tid >> 5;
    const int warpM = wid & 3;
    const int warpN = wid >> 2;
    const int g = lane >> 2;
    const int t = lane & 3;

    const int b  = blockIdx.y;
    const int s0 = blockIdx.x * 128;
    const int zAll = blockIdx.z;
    const bool isEnc = (zAll < 4);
    const int z  = zAll & 3;
    const int h0 = z * 128;

    const int K = isEnc ? D_ : F_;
    const __half* __restrict__ A_g = isEnc ? Ae : Af;
    const __half* __restrict__ Wh  = isEnc ? Weh_ : Wfh_;
    const __half* __restrict__ Wl  = isEnc ? Wel_ : Wfl_;
    const float* __restrict__ bias = isEnc ? be : bf;
    const float* __restrict__ st   = (isEnc ? g_stx : g_stf) + b * H_;

    const uint32_t tbase = smem_u32(smem) + TILES_OFF;

    if (tid < 128) { bias_sh[tid] = bias[h0 + tid]; st_sh[tid] = st[h0 + tid]; }

    const __half* __restrict__ Abh = A_g + ((size_t)b * S_ + s0) * K;

    float acc[2][8][4];
#pragma unroll
    for (int mt = 0; mt < 2; mt++)
#pragma unroll
        for (int nt = 0; nt < 8; nt++)
#pragma unroll
            for (int j = 0; j < 4; j++) acc[mt][nt][j] = 0.f;

    // Each 128x64 fp16 buffer = 1024 16B-chunks; 4 per thread per buffer.
    auto issue = [&](int ki, int buf) {
        const uint32_t base = tbase + (uint32_t)buf * STG_STRIDE;
        const int k0 = ki * 64;
#pragma unroll
        for (int p = 0; p < 4; p++) {
            int idx = p * 256 + tid;
            int r = idx >> 3, c = idx & 7;
            uint32_t doff = (uint32_t)r * 144 + c * 16;
            CP16(base +         doff, Abh + (size_t)r * K + k0 + c * 8);
            CP16(base + 18432 + doff, Wh + (size_t)(h0 + r) * K + k0 + c * 8);
            CP16(base + 36864 + doff, Wl + (size_t)(h0 + r) * K + k0 + c * 8);
        }
    };

    const int NK = K / 64;

    issue(0, 0);
    CP_COMMIT();

    for (int ki = 0; ki < NK; ki++) {
        if (ki > 0) __syncthreads();   // all warps done with stage ki-1 before buf reuse
        if (ki + 1 < NK) {
            issue(ki + 1, (ki + 1) & 1);
            CP_COMMIT();
            CP_WAIT1();    // stage ki landed; ki+1 in flight
        } else {
            CP_WAIT0();
        }
        __syncthreads();   // tile visible to all warps

        const uint32_t sb = tbase + (uint32_t)(ki & 1) * STG_STRIDE;
#pragma unroll
        for (int kk = 0; kk < 4; kk++) {
            const int kb = kk * 16;     // fp16 elems within the 64-wide tile
            uint32_t ah[2][4];
#pragma unroll
            for (int mt = 0; mt < 2; mt++) {
                int row = warpM * 32 + mt * 16 + (lane & 15);
                uint32_t a_addr = sb + (uint32_t)row * 144
                                + ((uint32_t)kb + ((lane >> 4) << 3)) * 2;
                ldsm_x4(ah[mt], a_addr);
            }
#pragma unroll
            for (int ntg = 0; ntg < 2; ntg++) {
                int nrow = warpN * 64 + ntg * 32 + lane;
                uint32_t b_addr = sb + 18432 + (uint32_t)nrow * 144 + kb * 2;
                uint32_t bh0[4], bh1[4], bl0[4], bl1[4];
                ldsm_x4(bh0, b_addr);
                ldsm_x4(bh1, b_addr + 16);
                ldsm_x4(bl0, b_addr + 18432);
                ldsm_x4(bl1, b_addr + 18432 + 16);
                // hi pass then lo pass (per-accumulator order: hi, lo)
#pragma unroll
                for (int i = 0; i < 4; i++)
#pragma unroll
                    for (int mt = 0; mt < 2; mt++)
                        mma_f16(acc[mt][ntg * 4 + i], ah[mt], bh0[i], bh1[i]);
#pragma unroll
                for (int i = 0; i < 4; i++)
#pragma unroll
                    for (int mt = 0; mt < 2; mt++)
                        mma_f16(acc[mt][ntg * 4 + i], ah[mt], bl0[i], bl1[i]);
            }
        }
    }

    // ---- epilogue: tanh(+bias) . state over this CTA's 128 h ----
    float scoreRow[4] = {0.f, 0.f, 0.f, 0.f};
#pragma unroll
    for (int mt = 0; mt < 2; mt++)
#pragma unroll
        for (int nt = 0; nt < 8; nt++)
#pragma unroll
            for (int j = 0; j < 4; j++) {
                int hh = warpN * 64 + nt * 8 + 2 * t + (j & 1);
                float v = tanhf(acc[mt][nt][j] + bias_sh[hh]) * st_sh[hh];
                scoreRow[mt * 2 + (j >> 1)] += v;
            }

    // Reduce across the 4 t-lanes of each quad (same row g)
#pragma unroll
    for (int off = 1; off < 4; off <<= 1)
#pragma unroll
        for (int i = 0; i < 4; i++)
            scoreRow[i] += __shfl_xor_sync(0xffffffffu, scoreRow[i], off);

    // Combine warpN halves via smem, write this z-slab's partial scores
    __syncthreads();
    if (t == 0 && warpN == 1) {
#pragma unroll
        for (int mt = 0; mt < 2; mt++)
#pragma unroll
            for (int rh = 0; rh < 2; rh++) {
                int r = warpM * 32 + mt * 16 + rh * 8 + g;
                partial_sh[r] = scoreRow[mt * 2 + rh];
            }
    }
    __syncthreads();
    if (t == 0 && warpN == 0) {
        float* scoreOut = (isEnc ? g_se4 : g_sf4) + (size_t)z * (S_ * B_);
#pragma unroll
        for (int mt = 0; mt < 2; mt++)
#pragma unroll
            for (int rh = 0; rh < 2; rh++) {
                int r = warpM * 32 + mt * 16 + rh * 8 + g;
                scoreOut[(size_t)(s0 + r) * B_ + b] =
                    scoreRow[mt * 2 + rh] + partial_sh[r];
            }
    }
}

// ---------------------------------------------------------------------------
// K3: dual softmax + gamma (sums the 4 partial-score slabs, fixed order)
// ---------------------------------------------------------------------------
__global__ void gamma_kernel(float* __restrict__ gamma_out)
{
    __shared__ float red[256];
    __shared__ float tbuf[S_];
    const int b = blockIdx.x, tid = threadIdx.x;
    constexpr int SB = S_ * B_;

    float se[4], sf[4];
    float mE = -1e30f, mF = -1e30f;
#pragma unroll
    for (int i = 0; i < 4; i++) {
        int s = tid + i * 256;
        int idx = s * B_ + b;
        se[i] = ((g_se4[idx] + g_se4[SB + idx]) + (g_se4[2 * SB + idx] + g_se4[3 * SB + idx]));
        sf[i] = ((g_sf4[idx] + g_sf4[SB + idx]) + (g_sf4[2 * SB + idx] + g_sf4[3 * SB + idx]));
        mE = fmaxf(mE, se[i]);
        mF = fmaxf(mF, sf[i]);
    }
    auto blockMax = [&](float v) -> float {
        red[tid] = v; __syncthreads();
        for (int st = 128; st > 0; st >>= 1) {
            if (tid < st) red[tid] = fmaxf(red[tid], red[tid + st]);
            __syncthreads();
        }
        float r = red[0]; __syncthreads(); return r;
    };
    auto blockSum = [&](float v) -> float {
        red[tid] = v; __syncthreads();
        for (int st = 128; st > 0; st >>= 1) {
            if (tid < st) red[tid] += red[tid + st];
            __syncthreads();
        }
        float r = red[0]; __syncthreads(); return r;
    };
    mE = blockMax(mE);
    mF = blockMax(mF);

    float ze = 0.f, zf = 0.f, p = 0.f;
#pragma unroll
    for (int i = 0; i < 4; i++) {
        float ee = expf(se[i] - mE);
        float ef = expf(sf[i] - mF);
        ze += ee; zf += ef;
        float t = ee * ef;
        p += t;
        tbuf[tid + i * 256] = t;
    }
    ze = blockSum(ze);
    zf = blockSum(zf);
    p  = blockSum(p);

    float inv = 1.0f / (p + 1e-6f * ze * zf);
#pragma unroll
    for (int i = 0; i < 4; i++) {
        int s = tid + i * 256;
        gamma_out[s * B_ + b] = tbuf[s] * inv;
    }
}

// ---------------------------------------------------------------------------
// K4: context from fp16 activations (half traffic), S split 4 ways (slabs)
// ---------------------------------------------------------------------------
__global__ void context_kernel(const __half* __restrict__ Ae,
                               const float* __restrict__ gamma)
{
    __shared__ float gs[256];
    const int b = blockIdx.x, q = blockIdx.y, d = threadIdx.x;
    if (d < 256) gs[d] = gamma[(q * 256 + d) * B_ + b];
    __syncthreads();
    const __half* __restrict__ e = Ae + ((size_t)b * S_ + q * 256) * D_;
    float acc = 0.f;
#pragma unroll 4
    for (int s = 0; s < 256; s++)
        acc += gs[s] * __half2float(e[(size_t)s * D_ + d]);
    g_ctx4[q][b * D_ + d] = acc;
}

// ---------------------------------------------------------------------------
// K5: output GEMM + tanh (sums the 4 context slabs, fixed order)
// ---------------------------------------------------------------------------
__global__ void out_kernel(const float* __restrict__ x,
                           const float* __restrict__ Wg, const float* __restrict__ bg,
                           float* __restrict__ out)
{
    __shared__ float cx[2 * D_];
    const int b = blockIdx.x, h = threadIdx.x;
    cx[h] = (g_ctx4[0][b * D_ + h] + g_ctx4[1][b * D_ + h])
          + (g_ctx4[2][b * D_ + h] + g_ctx4[3][b * D_ + h]);
    cx[D_ + h] = x[b * D_ + h];
    __syncthreads();
    float acc = bg[h];
#pragma unroll 8
    for (int k = 0; k < 2 * D_; k++)
        acc += cx[k] * Wg[(size_t)k * H_ + h];
    out[b * H_ + h] = tanhf(acc);
}

// ---------------------------------------------------------------------------
extern "C" void kernel_launch(void* const* d_in, const int* in_sizes, int n_in,
                              void* d_out, int out_size)
{
    const float* x    = (const float*)d_in[0];
    const float* enc  = (const float*)d_in[1];
    const float* fld  = (const float*)d_in[2];
    const float* Wf   = (const float*)d_in[3];
    const float* bf   = (const float*)d_in[4];
    const float* We   = (const float*)d_in[5];
    const float* be   = (const float*)d_in[6];
    const float* Wsf  = (const float*)d_in[7];
    const float* bsf  = (const float*)d_in[8];
    const float* Wse  = (const float*)d_in[9];
    const float* bse  = (const float*)d_in[10];
    const float* Wg   = (const float*)d_in[11];
    const float* bg   = (const float*)d_in[12];

    float* out    = (float*)d_out;
    float* gammas = out + B_ * H_;

    static cudaStream_t s1 = nullptr, s2 = nullptr;
    static cudaEvent_t evFork = nullptr, evS1 = nullptr, evS2 = nullptr;
    static int init_done = 0;
    if (!init_done) {
        cudaFuncSetAttribute(score_mma,
                             cudaFuncAttributeMaxDynamicSharedMemorySize, SMEM_DYN);
        cudaStreamCreateWithFlags(&s1, cudaStreamNonBlocking);
        cudaStreamCreateWithFlags(&s2, cudaStreamNonBlocking);
        cudaEventCreateWithFlags(&evFork, cudaEventDisableTiming);
        cudaEventCreateWithFlags(&evS1,   cudaEventDisableTiming);
        cudaEventCreateWithFlags(&evS2,   cudaEventDisableTiming);
        init_done = 1;
    }

    // Resolve device-global addresses (host-side, no allocation)
    __half *pWeh, *pWel, *pWfh, *pWfl, *pAeh, *pAfh;
    cudaGetSymbolAddress((void**)&pWeh, g_Weh);
    cudaGetSymbolAddress((void**)&pWel, g_Wel);
    cudaGetSymbolAddress((void**)&pWfh, g_Wfh);
    cudaGetSymbolAddress((void**)&pWfl, g_Wfl);
    cudaGetSymbolAddress((void**)&pAeh, g_Aeh);
    cudaGetSymbolAddress((void**)&pAfh, g_Afh);

    // Fork s1 (fields branch) and s2 (state) off the default stream.
    cudaEventRecord(evFork, 0);
    cudaStreamWaitEvent(s1, evFork, 0);
    cudaStreamWaitEvent(s2, evFork, 0);

    // default stream: enc branch
    wconv_kernel<<<H_, 256>>>(We, pWeh, pWel, D_);
    aconv_kernel<<<(B_ * S_ * D_) / 1024, 256>>>(enc, pAeh);

    // s1: fields branch
    wconv_kernel<<<H_, 256, 0, s1>>>(Wf, pWfh, pWfl, F_);
    aconv_kernel<<<(B_ * S_ * F_) / 1024, 256, 0, s1>>>(fld, pAfh);

    // s2: state vectors
    state_kernel<<<B_, 512, 0, s2>>>(x, Wsf, bsf, Wse, bse);

    // Join everything into the default stream before the merged score GEMM.
    cudaEventRecord(evS1, s1);
    cudaEventRecord(evS2, s2);
    cudaStreamWaitEvent(0, evS1, 0);
    cudaStreamWaitEvent(0, evS2, 0);

    // Single merged score launch: z 0..3 enc (long CTAs first), 4..7 fields.
    dim3 sgrid(S_ / 128, B_, 8);
    score_mma<<<sgrid, 256, SMEM_DYN>>>(pAeh, pWeh, pWel, be,
                                        pAfh, pWfh, pWfl, bf);

    // Tail: softmax/gamma -> context -> output (default stream)
    gamma_kernel<<<B_, 256>>>(gammas);
    dim3 cgrid(B_, 4);
    context_kernel<<<cgrid, 512>>>(pAeh, gammas);
    out_kernel<<<B_, 512>>>(x, Wg, bg, out);
}